// round 14
// baseline (speedup 1.0000x reference)
#include <cuda_runtime.h>
#include <cuda_bf16.h>
#include <cuda_fp16.h>
#include <math.h>

// Problem constants
#define BATCH 512
#define SEQ   256
#define CDIM  384
#define HDIM  384
#define M_TOTAL (BATCH * SEQ)   // 131072

// ---------------------------------------------------------------------------
// Device scratch (static: runtime allocation is forbidden)
// q/k/v single fp16 (fp16 MMA is exact given fp16 inputs; quantization 1.4e-4)
// ---------------------------------------------------------------------------
__device__ __half g_q[(size_t)M_TOTAL * HDIM];
__device__ __half g_k[(size_t)M_TOTAL * HDIM];
__device__ __half g_v[(size_t)M_TOTAL * HDIM];
__device__ __half g_x[(size_t)M_TOTAL * CDIM];          // X as fp16
__device__ __half g_w[(size_t)3 * HDIM * CDIM];         // W transposed [w][n][k], fp16

// ---------------------------------------------------------------------------
// PTX helpers (portable to plain sm_103 target — NO tcgen05)
// ---------------------------------------------------------------------------
__device__ __forceinline__ unsigned int smem_u32(const void* p) {
    unsigned int a;
    asm("{ .reg .u64 t; cvta.to.shared.u64 t, %1; cvt.u32.u64 %0, t; }" : "=r"(a) : "l"(p));
    return a;
}
__device__ __forceinline__ void cp16(unsigned int dst, const void* src) {
    asm volatile("cp.async.cg.shared.global [%0], [%1], 16;" :: "r"(dst), "l"(src));
}
__device__ __forceinline__ void cp_commit() {
    asm volatile("cp.async.commit_group;" ::: "memory");
}
__device__ __forceinline__ void cp_wait0() {
    asm volatile("cp.async.wait_group 0;" ::: "memory");
}
__device__ __forceinline__ void cp_wait1() {
    asm volatile("cp.async.wait_group 1;" ::: "memory");
}
__device__ __forceinline__ void ldsm_x4(unsigned int* r, unsigned int addr) {
    asm volatile("ldmatrix.sync.aligned.m8n8.x4.shared.b16 {%0,%1,%2,%3}, [%4];"
                 : "=r"(r[0]), "=r"(r[1]), "=r"(r[2]), "=r"(r[3]) : "r"(addr));
}
__device__ __forceinline__ void ldsm_x4_t(unsigned int* r, unsigned int addr) {
    asm volatile("ldmatrix.sync.aligned.m8n8.x4.trans.shared.b16 {%0,%1,%2,%3}, [%4];"
                 : "=r"(r[0]), "=r"(r[1]), "=r"(r[2]), "=r"(r[3]) : "r"(addr));
}
__device__ __forceinline__ void mma_fp16(float* c, const unsigned int* a,
                                         const unsigned int* b) {
    asm volatile("mma.sync.aligned.m16n8k16.row.col.f32.f16.f16.f32 "
                 "{%0,%1,%2,%3}, {%4,%5,%6,%7}, {%8,%9}, {%0,%1,%2,%3};"
                 : "+f"(c[0]), "+f"(c[1]), "+f"(c[2]), "+f"(c[3])
                 : "r"(a[0]), "r"(a[1]), "r"(a[2]), "r"(a[3]), "r"(b[0]), "r"(b[1]));
}

// ---------------------------------------------------------------------------
// Prepass 1: X fp32 -> fp16
// ---------------------------------------------------------------------------
__global__ __launch_bounds__(256) void cvt_x_kernel(const float* __restrict__ X)
{
    size_t i = (size_t)blockIdx.x * 256 + threadIdx.x;   // over M*C/4
    float4 v = ((const float4*)X)[i];
    __half2* d = (__half2*)(g_x + 4 * i);
    d[0] = __floats2half2_rn(v.x, v.y);
    d[1] = __floats2half2_rn(v.z, v.w);
}

// ---------------------------------------------------------------------------
// Prepass 2: W fp32 [k][n] -> transposed fp16 [w][n][k]
// ---------------------------------------------------------------------------
__global__ __launch_bounds__(256) void cvt_w_kernel(const float* __restrict__ Wq,
                                                    const float* __restrict__ Wk,
                                                    const float* __restrict__ Wv)
{
    int i = blockIdx.x * 256 + threadIdx.x;     // < 3*384*384
    int w = i / (CDIM * HDIM);
    int r = i - w * (CDIM * HDIM);
    int k = r / HDIM;
    int n = r - k * HDIM;
    const float* W = (w == 0) ? Wq : ((w == 1) ? Wk : Wv);
    g_w[((size_t)w * HDIM + n) * CDIM + k] = __float2half_rn(W[(size_t)k * HDIM + n]);
}

// ---------------------------------------------------------------------------
// Kernel: QKV GEMM via fp16 mma.sync. CTA tile 128(M) x 64(N), 8 warps as
// 4m x 2n -> warp tile 32x32 (acc=32 regs). 2-stage pipeline, K chunks of 64.
// Smem/stage: A 128x144 (18432) + B 64x144 (9216) = 27648; x2 = 55296
// -> 4 CTAs/SM = 32 warps (50% occ), launch_bounds(256,4) caps regs at 64.
// ---------------------------------------------------------------------------
#define ROWB    144           // padded row stride (64 fp16 = 128B data + 16 pad)
#define QA_TILE (128 * ROWB)  // 18432
#define QB_TILE (64 * ROWB)   // 9216
#define QSTG    (QA_TILE + QB_TILE)        // 27648
#define QKV_SMEM_BYTES (2 * QSTG)          // 55296
#define NCHK    6

__global__ __launch_bounds__(256, 4) void qkv_mma_kernel()
{
    extern __shared__ char smem[];
    const unsigned int sb = smem_u32(smem);
    const int t    = threadIdx.x;
    const int wid  = t >> 5;
    const int lane = t & 31;

    const int nblk = blockIdx.x;           // 0..17
    const int w    = nblk / 6;             // weight select
    const int n0   = (nblk - w * 6) * 64;  // col offset within weight
    const int m0   = blockIdx.y * 128;

    const __half* wsrc = g_w + (size_t)w * HDIM * CDIM;

    const int wm = (wid & 3) * 32;         // 4 m-warps, 32 rows
    const int wn = (wid >> 2) * 32;        // 2 n-warps, 32 cols

    const unsigned int a_lane = (unsigned)((lane & 15) * ROWB + (lane >> 4) * 16);
    const unsigned int b_lane = (unsigned)(((lane & 7) + ((lane >> 4) << 3)) * ROWB
                                           + ((lane >> 3) & 1) * 16);

    float acc[2][4][4];
    #pragma unroll
    for (int mt = 0; mt < 2; mt++)
        #pragma unroll
        for (int nt = 0; nt < 4; nt++)
            #pragma unroll
            for (int q = 0; q < 4; q++) acc[mt][nt][q] = 0.0f;

    auto load_chunk = [&](int c, int stage) {
        const unsigned int s0 = sb + (unsigned)stage * QSTG;
        // A: 128 rows x 8 x 16B = 1024 cp16 (4/thread)
        #pragma unroll
        for (int it = 0; it < 4; it++) {
            int s = t + it * 256;
            int r = s >> 3, j = s & 7;
            unsigned int d = (unsigned)(r * ROWB + j * 16);
            cp16(s0 + d, g_x + (size_t)(m0 + r) * CDIM + c * 64 + j * 8);
        }
        // B: 64 rows x 8 x 16B = 512 cp16 (2/thread)
        #pragma unroll
        for (int it = 0; it < 2; it++) {
            int s = t + it * 256;
            int r = s >> 3, j = s & 7;
            unsigned int d = (unsigned)(r * ROWB + j * 16);
            cp16(s0 + QA_TILE + d, wsrc + (size_t)(n0 + r) * CDIM + c * 64 + j * 8);
        }
        cp_commit();
    };

    load_chunk(0, 0);
    load_chunk(1, 1);

    for (int c = 0; c < NCHK; c++) {
        if (c + 1 < NCHK) cp_wait1(); else cp_wait0();
        __syncthreads();

        const unsigned int sa  = sb + (unsigned)(c & 1) * QSTG;
        const unsigned int sbb = sa + QA_TILE;

        #pragma unroll
        for (int kk = 0; kk < 4; kk++) {
            const unsigned int koff = kk * 32;
            unsigned int Af[2][4];
            #pragma unroll
            for (int mt = 0; mt < 2; mt++) {
                unsigned int ab = (unsigned)((wm + mt * 16) * ROWB) + koff + a_lane;
                ldsm_x4(Af[mt], sa + ab);
            }
            #pragma unroll
            for (int nt2 = 0; nt2 < 2; nt2++) {
                unsigned int bb = (unsigned)((wn + nt2 * 16) * ROWB) + koff + b_lane;
                unsigned int Bf[4];
                ldsm_x4(Bf, sbb + bb);
                #pragma unroll
                for (int mt = 0; mt < 2; mt++) {
                    mma_fp16(acc[mt][nt2 * 2 + 0], Af[mt], Bf + 0);
                    mma_fp16(acc[mt][nt2 * 2 + 1], Af[mt], Bf + 2);
                }
            }
        }
        __syncthreads();

        if (c + 2 < NCHK) load_chunk(c + 2, c & 1);
    }

    // Epilogue: fp32 acc -> fp16 q/k/v
    __half* outp = (w == 0) ? g_q : ((w == 1) ? g_k : g_v);
    #pragma unroll
    for (int mt = 0; mt < 2; mt++) {
        int r0 = m0 + wm + mt * 16 + (lane >> 2);
        #pragma unroll
        for (int nt = 0; nt < 4; nt++) {
            int cc = n0 + wn + nt * 8 + 2 * (lane & 3);
            *(__half2*)(outp + (size_t)r0 * HDIM + cc) =
                __floats2half2_rn(acc[mt][nt][0], acc[mt][nt][1]);
            *(__half2*)(outp + (size_t)(r0 + 8) * HDIM + cc) =
                __floats2half2_rn(acc[mt][nt][2], acc[mt][nt][3]);
        }
    }
}

// ---------------------------------------------------------------------------
// Kernel: causal attention (R11 structure, 219us) + P->fp16 fused into the
// softmax normalize loop (removes one 64x256 smem pass + one barrier).
// Smem overlay (bytes):
//   phase A stages s=0,1 at s*46080: QB +0 (9216), KB +9216 (36864) -> 92160
//   phase B: PHI fp16 64x264 at [0,33792); Ps fp32 64x260 at [40960,107520)
//   phase C: VB stages at 40960 + s*36864 -> [40960,114688)
// ---------------------------------------------------------------------------
#define AT_STGS  46080u
#define AT_QB    0u
#define AT_KB    9216u
#define AT_PHI   0u
#define AT_PS    40960u
#define AT_VB0   40960u
#define AT_VBS   36864u
#define AT_SMEM_BYTES 114688

__global__ __launch_bounds__(256, 2) void attn_mma_kernel(float* __restrict__ Out)
{
    extern __shared__ char smem[];
    const unsigned int sb = smem_u32(smem);
    const int t    = threadIdx.x;
    const int wid  = t >> 5;
    const int lane = t & 31;
    const int bq   = blockIdx.x;          // 0..3
    const int b    = blockIdx.y;          // 0..511
    const int q0   = bq * 64;
    const int Kv   = (bq + 1) * 64;       // valid keys
    const float scl = rsqrtf((float)HDIM);

    const int wm = (wid & 1) * 32;        // warp m offset (2 m-warps)
    const int wn = (wid >> 1) * 64;       // warp n offset, phase A (4 n-warps)

    const unsigned int a_lane = (unsigned)((lane & 15) * ROWB + (lane >> 4) * 16);
    const unsigned int b_lane = (unsigned)(((lane & 7) + ((lane >> 4) << 3)) * ROWB
                                           + ((lane >> 3) & 1) * 16);
    const unsigned int p_lane = (unsigned)((lane & 15) * 528 + (lane >> 4) * 16);
    const unsigned int v_lane = (unsigned)((lane & 15) * ROWB + (lane >> 4) * 16);

    // ---------------- Phase A: S = Q K^T (fp16, double-buffered) -----------
    float sacc[2][8][4];
    #pragma unroll
    for (int mt = 0; mt < 2; mt++)
        #pragma unroll
        for (int nt = 0; nt < 8; nt++)
            #pragma unroll
            for (int q = 0; q < 4; q++) sacc[mt][nt][q] = 0.0f;

    const bool sact = (wn < Kv);

    auto load_qk = [&](int hc, int stg) {
        const unsigned int s0 = sb + (unsigned)stg * AT_STGS;
        #pragma unroll
        for (int it = 0; it < 2; it++) {
            int s = t + it * 256;
            int r = s >> 3, j = s & 7;
            unsigned int d = (unsigned)(r * ROWB + j * 16);
            cp16(s0 + AT_QB + d, g_q + (size_t)(b * SEQ + q0 + r) * HDIM + hc * 64 + j * 8);
        }
        #pragma unroll
        for (int it = 0; it < 8; it++) {
            int s = t + it * 256;
            int r = s >> 3, j = s & 7;
            if (r < Kv) {
                unsigned int d = (unsigned)(r * ROWB + j * 16);
                cp16(s0 + AT_KB + d, g_k + (size_t)(b * SEQ + r) * HDIM + hc * 64 + j * 8);
            }
        }
        cp_commit();
    };

    load_qk(0, 0);

    for (int hc = 0; hc < 6; hc++) {
        const int stg = hc & 1;
        if (hc + 1 < 6) load_qk(hc + 1, stg ^ 1);
        if (hc + 1 < 6) cp_wait1(); else cp_wait0();
        __syncthreads();

        if (sact) {
            const unsigned int sq = sb + (unsigned)stg * AT_STGS + AT_QB;
            const unsigned int sk = sb + (unsigned)stg * AT_STGS + AT_KB;
            #pragma unroll
            for (int kk = 0; kk < 4; kk++) {
                const unsigned int koff = kk * 32;
                unsigned int Af[2][4];
                #pragma unroll
                for (int mt = 0; mt < 2; mt++) {
                    unsigned int ab = (unsigned)((wm + mt * 16) * ROWB) + koff + a_lane;
                    ldsm_x4(Af[mt], sq + ab);
                }
                #pragma unroll
                for (int nt2 = 0; nt2 < 4; nt2++) {
                    unsigned int bb = (unsigned)((wn + nt2 * 16) * ROWB) + koff + b_lane;
                    unsigned int Bf[4];
                    ldsm_x4(Bf, sk + bb);
                    #pragma unroll
                    for (int mt = 0; mt < 2; mt++) {
                        mma_fp16(sacc[mt][nt2 * 2 + 0], Af[mt], Bf + 0);
                        mma_fp16(sacc[mt][nt2 * 2 + 1], Af[mt], Bf + 2);
                    }
                }
            }
        }
        __syncthreads();
    }

    // ---------------- Phase B: scatter S, softmax (+fused fp16 convert) ----
    float* Ps = (float*)(smem + AT_PS);
    #pragma unroll
    for (int mt = 0; mt < 2; mt++) {
        int r = wm + mt * 16 + (lane >> 2);
        #pragma unroll
        for (int nt = 0; nt < 8; nt++) {
            int cc = wn + nt * 8 + 2 * (lane & 3);
            *(float2*)&Ps[r * 260 + cc] =
                make_float2(sacc[mt][nt][0] * scl, sacc[mt][nt][1] * scl);
            *(float2*)&Ps[(r + 8) * 260 + cc] =
                make_float2(sacc[mt][nt][2] * scl, sacc[mt][nt][3] * scl);
        }
    }
    __syncthreads();

    {
        __half* Ph = (__half*)(smem + AT_PHI);
        const int wq = wid;                 // warp handles rows wq*8 .. wq*8+7
        for (int rr = 0; rr < 8; rr++) {
            int r  = wq * 8 + rr;
            int qg = q0 + r;                // valid keys: 0..qg
            float* row = Ps + (size_t)r * 260;
            float m = -1e30f;
            for (int j = lane; j <= qg; j += 32) m = fmaxf(m, row[j]);
            #pragma unroll
            for (int off = 16; off > 0; off >>= 1)
                m = fmaxf(m, __shfl_xor_sync(0xffffffffu, m, off));
            float s = 0.0f;
            for (int j = lane; j <= qg; j += 32) {
                float e = __expf(row[j] - m);
                row[j] = e;
                s += e;
            }
            #pragma unroll
            for (int off = 16; off > 0; off >>= 1)
                s += __shfl_xor_sync(0xffffffffu, s, off);
            float inv = 1.0f / s;
            // normalize + convert to fp16 in one pass (PHI overlays dead QB/KB)
            __half* prow = Ph + (size_t)r * 264;
            for (int j = lane; j < Kv; j += 32)
                prow[j] = (j <= qg) ? __float2half_rn(row[j] * inv) : __half(0);
        }
    }
    __syncthreads();

    // ---------------- Phase C: O = P V (fp16, double-buffered V) -----------
    const int wnc = (wid >> 1) * 16;        // warp n offset within 64-col chunk
    const int nks = Kv >> 4;                // k16 steps over keys

    auto load_v = [&](int hc, int stg) {
        const unsigned int v0 = sb + AT_VB0 + (unsigned)stg * AT_VBS;
        #pragma unroll
        for (int it = 0; it < 8; it++) {
            int s = t + it * 256;
            int r = s >> 3, j = s & 7;
            if (r < Kv) {
                unsigned int d = (unsigned)(r * ROWB + j * 16);
                cp16(v0 + d, g_v + (size_t)(b * SEQ + r) * HDIM + hc * 64 + j * 8);
            }
        }
        cp_commit();
    };

    load_v(0, 0);

    for (int hc = 0; hc < 6; hc++) {
        const int stg = hc & 1;
        if (hc + 1 < 6) load_v(hc + 1, stg ^ 1);
        if (hc + 1 < 6) cp_wait1(); else cp_wait0();
        __syncthreads();

        const unsigned int sv = sb + AT_VB0 + (unsigned)stg * AT_VBS;

        float oacc[2][2][4];
        #pragma unroll
        for (int mt = 0; mt < 2; mt++)
            #pragma unroll
            for (int nt = 0; nt < 2; nt++)
                #pragma unroll
                for (int q = 0; q < 4; q++) oacc[mt][nt][q] = 0.0f;

        for (int ks = 0; ks < nks; ks++) {
            unsigned int Phf[2][4];
            #pragma unroll
            for (int mt = 0; mt < 2; mt++) {
                unsigned int pa = (unsigned)((wm + mt * 16) * 528) + ks * 32 + p_lane;
                ldsm_x4(Phf[mt], sb + AT_PHI + pa);
            }
            unsigned int Vh[4];
            unsigned int va = (unsigned)(ks * 16 * ROWB) + (unsigned)(wnc * 2) + v_lane;
            ldsm_x4_t(Vh, sv + va);
            #pragma unroll
            for (int mt = 0; mt < 2; mt++) {
                #pragma unroll
                for (int nt = 0; nt < 2; nt++) {
                    mma_fp16(oacc[mt][nt], Phf[mt], Vh + nt * 2);
                }
            }
        }

        // write O chunk
        #pragma unroll
        for (int mt = 0; mt < 2; mt++) {
            int gr = b * SEQ + q0 + wm + mt * 16 + (lane >> 2);
            #pragma unroll
            for (int nt = 0; nt < 2; nt++) {
                int gc = hc * 64 + wnc + nt * 8 + 2 * (lane & 3);
                *(float2*)(Out + (size_t)gr * HDIM + gc) =
                    make_float2(oacc[mt][nt][0], oacc[mt][nt][1]);
                *(float2*)(Out + (size_t)(gr + 8) * HDIM + gc) =
                    make_float2(oacc[mt][nt][2], oacc[mt][nt][3]);
            }
        }
        __syncthreads();
    }
}

// ---------------------------------------------------------------------------
// Launch
// ---------------------------------------------------------------------------
extern "C" void kernel_launch(void* const* d_in, const int* in_sizes, int n_in,
                              void* d_out, int out_size)
{
    const float* x  = (const float*)d_in[0];
    const float* Wq = (const float*)d_in[1];
    const float* Wk = (const float*)d_in[2];
    const float* Wv = (const float*)d_in[3];
    float* out = (float*)d_out;

    cvt_x_kernel<<<(M_TOTAL * CDIM) / 1024, 256>>>(x);
    cvt_w_kernel<<<(3 * CDIM * HDIM) / 256, 256>>>(Wq, Wk, Wv);

    cudaFuncSetAttribute(qkv_mma_kernel, cudaFuncAttributeMaxDynamicSharedMemorySize,
                         QKV_SMEM_BYTES);
    qkv_mma_kernel<<<dim3(18, M_TOTAL / 128), 256, QKV_SMEM_BYTES>>>();

    cudaFuncSetAttribute(attn_mma_kernel, cudaFuncAttributeMaxDynamicSharedMemorySize,
                         AT_SMEM_BYTES);
    attn_mma_kernel<<<dim3(SEQ / 64, BATCH), 256, AT_SMEM_BYTES>>>(out);
}

// round 15
// speedup vs baseline: 1.0421x; 1.0421x over previous
#include <cuda_runtime.h>
#include <cuda_bf16.h>
#include <cuda_fp16.h>
#include <math.h>

// Problem constants
#define BATCH 512
#define SEQ   256
#define CDIM  384
#define HDIM  384
#define M_TOTAL (BATCH * SEQ)   // 131072

// ---------------------------------------------------------------------------
// Device scratch (static: runtime allocation is forbidden)
// ---------------------------------------------------------------------------
__device__ __half g_q[(size_t)M_TOTAL * HDIM];
__device__ __half g_k[(size_t)M_TOTAL * HDIM];
__device__ __half g_v[(size_t)M_TOTAL * HDIM];
__device__ __half g_x[(size_t)M_TOTAL * CDIM];          // X as fp16
__device__ __half g_w[(size_t)3 * HDIM * CDIM];         // W transposed [w][n][k], fp16

// ---------------------------------------------------------------------------
// PTX helpers (portable to plain sm_103 target — NO tcgen05)
// ---------------------------------------------------------------------------
__device__ __forceinline__ unsigned int smem_u32(const void* p) {
    unsigned int a;
    asm("{ .reg .u64 t; cvta.to.shared.u64 t, %1; cvt.u32.u64 %0, t; }" : "=r"(a) : "l"(p));
    return a;
}
__device__ __forceinline__ void cp16(unsigned int dst, const void* src) {
    asm volatile("cp.async.cg.shared.global [%0], [%1], 16;" :: "r"(dst), "l"(src));
}
__device__ __forceinline__ void cp_commit() {
    asm volatile("cp.async.commit_group;" ::: "memory");
}
__device__ __forceinline__ void cp_wait0() {
    asm volatile("cp.async.wait_group 0;" ::: "memory");
}
__device__ __forceinline__ void cp_wait1() {
    asm volatile("cp.async.wait_group 1;" ::: "memory");
}
__device__ __forceinline__ void ldsm_x4(unsigned int* r, unsigned int addr) {
    asm volatile("ldmatrix.sync.aligned.m8n8.x4.shared.b16 {%0,%1,%2,%3}, [%4];"
                 : "=r"(r[0]), "=r"(r[1]), "=r"(r[2]), "=r"(r[3]) : "r"(addr));
}
__device__ __forceinline__ void ldsm_x4_t(unsigned int* r, unsigned int addr) {
    asm volatile("ldmatrix.sync.aligned.m8n8.x4.trans.shared.b16 {%0,%1,%2,%3}, [%4];"
                 : "=r"(r[0]), "=r"(r[1]), "=r"(r[2]), "=r"(r[3]) : "r"(addr));
}
__device__ __forceinline__ void mma_fp16(float* c, const unsigned int* a,
                                         const unsigned int* b) {
    asm volatile("mma.sync.aligned.m16n8k16.row.col.f32.f16.f16.f32 "
                 "{%0,%1,%2,%3}, {%4,%5,%6,%7}, {%8,%9}, {%0,%1,%2,%3};"
                 : "+f"(c[0]), "+f"(c[1]), "+f"(c[2]), "+f"(c[3])
                 : "r"(a[0]), "r"(a[1]), "r"(a[2]), "r"(a[3]), "r"(b[0]), "r"(b[1]));
}

// ---------------------------------------------------------------------------
// Prepass 1: X fp32 -> fp16
// ---------------------------------------------------------------------------
__global__ __launch_bounds__(256) void cvt_x_kernel(const float* __restrict__ X)
{
    size_t i = (size_t)blockIdx.x * 256 + threadIdx.x;   // over M*C/4
    float4 v = ((const float4*)X)[i];
    __half2* d = (__half2*)(g_x + 4 * i);
    d[0] = __floats2half2_rn(v.x, v.y);
    d[1] = __floats2half2_rn(v.z, v.w);
}

// ---------------------------------------------------------------------------
// Prepass 2: W fp32 [k][n] -> transposed fp16 [w][n][k]
// ---------------------------------------------------------------------------
__global__ __launch_bounds__(256) void cvt_w_kernel(const float* __restrict__ Wq,
                                                    const float* __restrict__ Wk,
                                                    const float* __restrict__ Wv)
{
    int i = blockIdx.x * 256 + threadIdx.x;     // < 3*384*384
    int w = i / (CDIM * HDIM);
    int r = i - w * (CDIM * HDIM);
    int k = r / HDIM;
    int n = r - k * HDIM;
    const float* W = (w == 0) ? Wq : ((w == 1) ? Wk : Wv);
    g_w[((size_t)w * HDIM + n) * CDIM + k] = __float2half_rn(W[(size_t)k * HDIM + n]);
}

// ---------------------------------------------------------------------------
// Kernel: QKV GEMM — REVERTED to the measured-best R11 config (~370us):
// CTA 128x128, warp tile 32x64, K chunks of 64, 2-stage pipeline, 2 CTAs/SM.
// ---------------------------------------------------------------------------
#define ROWB   144            // padded row stride (64 fp16 = 128B data + 16 pad)
#define QTILE  (128 * ROWB)   // 18432 bytes per operand tile
#define QSTG   (2 * QTILE)    // 36864 per stage
#define QKV_SMEM_BYTES (2 * QSTG)   // 73728
#define NCHK   6

__global__ __launch_bounds__(256, 2) void qkv_mma_kernel()
{
    extern __shared__ char smem[];
    const unsigned int sb = smem_u32(smem);
    const int t    = threadIdx.x;
    const int wid  = t >> 5;
    const int lane = t & 31;

    const int nblk = blockIdx.x;           // 0..8
    const int w    = nblk / 3;             // weight select
    const int n0   = (nblk - w * 3) * 128; // col offset within weight
    const int m0   = blockIdx.y * 128;

    const __half* wsrc = g_w + (size_t)w * HDIM * CDIM;

    const int wm = (wid & 3) * 32;
    const int wn = (wid >> 2) * 64;

    const unsigned int a_lane = (unsigned)((lane & 15) * ROWB + (lane >> 4) * 16);
    const unsigned int b_lane = (unsigned)(((lane & 7) + ((lane >> 4) << 3)) * ROWB
                                           + ((lane >> 3) & 1) * 16);

    float acc[2][8][4];
    #pragma unroll
    for (int mt = 0; mt < 2; mt++)
        #pragma unroll
        for (int nt = 0; nt < 8; nt++)
            #pragma unroll
            for (int q = 0; q < 4; q++) acc[mt][nt][q] = 0.0f;

    auto load_chunk = [&](int c, int stage) {
        const unsigned int s0 = sb + (unsigned)stage * QSTG;
        #pragma unroll
        for (int it = 0; it < 4; it++) {
            int s = t + it * 256;
            int r = s >> 3, j = s & 7;
            unsigned int d = (unsigned)(r * ROWB + j * 16);
            cp16(s0 + d,         g_x + (size_t)(m0 + r) * CDIM + c * 64 + j * 8);
            cp16(s0 + QTILE + d, wsrc + (size_t)(n0 + r) * CDIM + c * 64 + j * 8);
        }
        cp_commit();
    };

    load_chunk(0, 0);
    load_chunk(1, 1);

    for (int c = 0; c < NCHK; c++) {
        if (c + 1 < NCHK) cp_wait1(); else cp_wait0();
        __syncthreads();

        const unsigned int sa = sb + (unsigned)(c & 1) * QSTG;
        const unsigned int sbb = sa + QTILE;

        #pragma unroll
        for (int kk = 0; kk < 4; kk++) {
            const unsigned int koff = kk * 32;
            unsigned int Af[2][4];
            #pragma unroll
            for (int mt = 0; mt < 2; mt++) {
                unsigned int ab = (unsigned)((wm + mt * 16) * ROWB) + koff + a_lane;
                ldsm_x4(Af[mt], sa + ab);
            }
            #pragma unroll
            for (int nt2 = 0; nt2 < 4; nt2++) {
                unsigned int bb = (unsigned)((wn + nt2 * 16) * ROWB) + koff + b_lane;
                unsigned int Bf[4];
                ldsm_x4(Bf, sbb + bb);
                #pragma unroll
                for (int mt = 0; mt < 2; mt++) {
                    mma_fp16(acc[mt][nt2 * 2 + 0], Af[mt], Bf + 0);
                    mma_fp16(acc[mt][nt2 * 2 + 1], Af[mt], Bf + 2);
                }
            }
        }
        __syncthreads();

        if (c + 2 < NCHK) load_chunk(c + 2, c & 1);
    }

    // Epilogue: fp32 acc -> fp16 q/k/v
    __half* outp = (w == 0) ? g_q : ((w == 1) ? g_k : g_v);
    #pragma unroll
    for (int mt = 0; mt < 2; mt++) {
        int r0 = m0 + wm + mt * 16 + (lane >> 2);
        #pragma unroll
        for (int nt = 0; nt < 8; nt++) {
            int cc = n0 + wn + nt * 8 + 2 * (lane & 3);
            *(__half2*)(outp + (size_t)r0 * HDIM + cc) =
                __floats2half2_rn(acc[mt][nt][0], acc[mt][nt][1]);
            *(__half2*)(outp + (size_t)(r0 + 8) * HDIM + cc) =
                __floats2half2_rn(acc[mt][nt][2], acc[mt][nt][3]);
        }
    }
}

// ---------------------------------------------------------------------------
// Kernel: causal attention, 128 QUERIES / 512 THREADS per CTA (grid 1024):
// halves per-query chunk/barrier/softmax overhead vs 64-query CTAs. Same
// warp-level structure and arithmetic order as the 207us R14 kernel.
// 16 warps: phase A 4m x 4n (warp tile 32x64); softmax 16x8 rows; phase C
// 4m x 4n. Double-buffered QK and V chunk streams; P->fp16 fused in softmax.
// Smem overlay (bytes):
//   phase A stages s=0,1 at s*55296: QB +0 (18432), KB +18432 (36864)
//   phase B: PHI fp16 128x264 at [0,67584); Ps fp32 128x260 at [67584,200704)
//   phase C: VB stages at 67584 + s*36864 -> [67584,141312)
// Total 200704 (1 CTA/SM, 16 warps).
// ---------------------------------------------------------------------------
#define AT_STGS  55296u
#define AT_QB    0u
#define AT_KB    18432u
#define AT_PHI   0u
#define AT_PS    67584u
#define AT_VB0   67584u
#define AT_VBS   36864u
#define AT_SMEM_BYTES 200704

__global__ __launch_bounds__(512, 1) void attn_mma_kernel(float* __restrict__ Out)
{
    extern __shared__ char smem[];
    const unsigned int sb = smem_u32(smem);
    const int t    = threadIdx.x;
    const int wid  = t >> 5;              // 0..15
    const int lane = t & 31;
    const int bqh  = blockIdx.x;          // 0..1 (128-query tile)
    const int b    = blockIdx.y;          // 0..511
    const int q0   = bqh * 128;
    const int Kv   = q0 + 128;            // valid keys for this tile
    const float scl = rsqrtf((float)HDIM);

    const int wm = (wid & 3) * 32;        // 4 m-warp-groups over 128 rows
    const int wn = (wid >> 2) * 64;       // 4 n-warp-groups over 256 cols

    const unsigned int a_lane = (unsigned)((lane & 15) * ROWB + (lane >> 4) * 16);
    const unsigned int b_lane = (unsigned)(((lane & 7) + ((lane >> 4) << 3)) * ROWB
                                           + ((lane >> 3) & 1) * 16);
    const unsigned int p_lane = (unsigned)((lane & 15) * 528 + (lane >> 4) * 16);
    const unsigned int v_lane = (unsigned)((lane & 15) * ROWB + (lane >> 4) * 16);

    // ---------------- Phase A: S = Q K^T (fp16, double-buffered) -----------
    float sacc[2][8][4];
    #pragma unroll
    for (int mt = 0; mt < 2; mt++)
        #pragma unroll
        for (int nt = 0; nt < 8; nt++)
            #pragma unroll
            for (int q = 0; q < 4; q++) sacc[mt][nt][q] = 0.0f;

    const bool sact = (wn < Kv);

    auto load_qk = [&](int hc, int stg) {
        const unsigned int s0 = sb + (unsigned)stg * AT_STGS;
        // Q: 128 rows x 8 x 16B = 1024 cp16 (2/thread)
        #pragma unroll
        for (int it = 0; it < 2; it++) {
            int s = t + it * 512;
            int r = s >> 3, j = s & 7;
            unsigned int d = (unsigned)(r * ROWB + j * 16);
            cp16(s0 + AT_QB + d, g_q + (size_t)(b * SEQ + q0 + r) * HDIM + hc * 64 + j * 8);
        }
        // K: Kv rows x 8 x 16B (up to 2048 cp16, 4/thread)
        #pragma unroll
        for (int it = 0; it < 4; it++) {
            int s = t + it * 512;
            int r = s >> 3, j = s & 7;
            if (r < Kv) {
                unsigned int d = (unsigned)(r * ROWB + j * 16);
                cp16(s0 + AT_KB + d, g_k + (size_t)(b * SEQ + r) * HDIM + hc * 64 + j * 8);
            }
        }
        cp_commit();
    };

    load_qk(0, 0);

    for (int hc = 0; hc < 6; hc++) {
        const int stg = hc & 1;
        if (hc + 1 < 6) load_qk(hc + 1, stg ^ 1);
        if (hc + 1 < 6) cp_wait1(); else cp_wait0();
        __syncthreads();

        if (sact) {
            const unsigned int sq = sb + (unsigned)stg * AT_STGS + AT_QB;
            const unsigned int sk = sb + (unsigned)stg * AT_STGS + AT_KB;
            #pragma unroll
            for (int kk = 0; kk < 4; kk++) {
                const unsigned int koff = kk * 32;
                unsigned int Af[2][4];
                #pragma unroll
                for (int mt = 0; mt < 2; mt++) {
                    unsigned int ab = (unsigned)((wm + mt * 16) * ROWB) + koff + a_lane;
                    ldsm_x4(Af[mt], sq + ab);
                }
                #pragma unroll
                for (int nt2 = 0; nt2 < 4; nt2++) {
                    unsigned int bb = (unsigned)((wn + nt2 * 16) * ROWB) + koff + b_lane;
                    unsigned int Bf[4];
                    ldsm_x4(Bf, sk + bb);
                    #pragma unroll
                    for (int mt = 0; mt < 2; mt++) {
                        mma_fp16(sacc[mt][nt2 * 2 + 0], Af[mt], Bf + 0);
                        mma_fp16(sacc[mt][nt2 * 2 + 1], Af[mt], Bf + 2);
                    }
                }
            }
        }
        __syncthreads();
    }

    // ---------------- Phase B: scatter S, softmax (+fused fp16 convert) ----
    float* Ps = (float*)(smem + AT_PS);
    #pragma unroll
    for (int mt = 0; mt < 2; mt++) {
        int r = wm + mt * 16 + (lane >> 2);
        #pragma unroll
        for (int nt = 0; nt < 8; nt++) {
            int cc = wn + nt * 8 + 2 * (lane & 3);
            *(float2*)&Ps[r * 260 + cc] =
                make_float2(sacc[mt][nt][0] * scl, sacc[mt][nt][1] * scl);
            *(float2*)&Ps[(r + 8) * 260 + cc] =
                make_float2(sacc[mt][nt][2] * scl, sacc[mt][nt][3] * scl);
        }
    }
    __syncthreads();

    {
        __half* Ph = (__half*)(smem + AT_PHI);
        const int wq = wid;                 // warp handles rows wq*8 .. wq*8+7
        for (int rr = 0; rr < 8; rr++) {
            int r  = wq * 8 + rr;
            int qg = q0 + r;                // valid keys: 0..qg
            float* row = Ps + (size_t)r * 260;
            float m = -1e30f;
            for (int j = lane; j <= qg; j += 32) m = fmaxf(m, row[j]);
            #pragma unroll
            for (int off = 16; off > 0; off >>= 1)
                m = fmaxf(m, __shfl_xor_sync(0xffffffffu, m, off));
            float s = 0.0f;
            for (int j = lane; j <= qg; j += 32) {
                float e = __expf(row[j] - m);
                row[j] = e;
                s += e;
            }
            #pragma unroll
            for (int off = 16; off > 0; off >>= 1)
                s += __shfl_xor_sync(0xffffffffu, s, off);
            float inv = 1.0f / s;
            // normalize + convert to fp16 in one pass (PHI overlays dead stages)
            __half* prow = Ph + (size_t)r * 264;
            for (int j = lane; j < Kv; j += 32)
                prow[j] = (j <= qg) ? __float2half_rn(row[j] * inv) : __half(0);
        }
    }
    __syncthreads();

    // ---------------- Phase C: O = P V (fp16, double-buffered V) -----------
    const int wnc = (wid >> 2) * 16;        // warp n offset within 64-col chunk
    const int nks = Kv >> 4;                // k16 steps over keys

    auto load_v = [&](int hc, int stg) {
        const unsigned int v0 = sb + AT_VB0 + (unsigned)stg * AT_VBS;
        #pragma unroll
        for (int it = 0; it < 4; it++) {
            int s = t + it * 512;
            int r = s >> 3, j = s & 7;
            if (r < Kv) {
                unsigned int d = (unsigned)(r * ROWB + j * 16);
                cp16(v0 + d, g_v + (size_t)(b * SEQ + r) * HDIM + hc * 64 + j * 8);
            }
        }
        cp_commit();
    };

    load_v(0, 0);

    for (int hc = 0; hc < 6; hc++) {
        const int stg = hc & 1;
        if (hc + 1 < 6) load_v(hc + 1, stg ^ 1);
        if (hc + 1 < 6) cp_wait1(); else cp_wait0();
        __syncthreads();

        const unsigned int sv = sb + AT_VB0 + (unsigned)stg * AT_VBS;

        float oacc[2][2][4];
        #pragma unroll
        for (int mt = 0; mt < 2; mt++)
            #pragma unroll
            for (int nt = 0; nt < 2; nt++)
                #pragma unroll
                for (int q = 0; q < 4; q++) oacc[mt][nt][q] = 0.0f;

        for (int ks = 0; ks < nks; ks++) {
            unsigned int Phf[2][4];
            #pragma unroll
            for (int mt = 0; mt < 2; mt++) {
                unsigned int pa = (unsigned)((wm + mt * 16) * 528) + ks * 32 + p_lane;
                ldsm_x4(Phf[mt], sb + AT_PHI + pa);
            }
            unsigned int Vh[4];
            unsigned int va = (unsigned)(ks * 16 * ROWB) + (unsigned)(wnc * 2) + v_lane;
            ldsm_x4_t(Vh, sv + va);
            #pragma unroll
            for (int mt = 0; mt < 2; mt++) {
                #pragma unroll
                for (int nt = 0; nt < 2; nt++) {
                    mma_fp16(oacc[mt][nt], Phf[mt], Vh + nt * 2);
                }
            }
        }

        // write O chunk
        #pragma unroll
        for (int mt = 0; mt < 2; mt++) {
            int gr = b * SEQ + q0 + wm + mt * 16 + (lane >> 2);
            #pragma unroll
            for (int nt = 0; nt < 2; nt++) {
                int gc = hc * 64 + wnc + nt * 8 + 2 * (lane & 3);
                *(float2*)(Out + (size_t)gr * HDIM + gc) =
                    make_float2(oacc[mt][nt][0], oacc[mt][nt][1]);
                *(float2*)(Out + (size_t)(gr + 8) * HDIM + gc) =
                    make_float2(oacc[mt][nt][2], oacc[mt][nt][3]);
            }
        }
        __syncthreads();
    }
}

// ---------------------------------------------------------------------------
// Launch
// ---------------------------------------------------------------------------
extern "C" void kernel_launch(void* const* d_in, const int* in_sizes, int n_in,
                              void* d_out, int out_size)
{
    const float* x  = (const float*)d_in[0];
    const float* Wq = (const float*)d_in[1];
    const float* Wk = (const float*)d_in[2];
    const float* Wv = (const float*)d_in[3];
    float* out = (float*)d_out;

    cvt_x_kernel<<<(M_TOTAL * CDIM) / 1024, 256>>>(x);
    cvt_w_kernel<<<(3 * CDIM * HDIM) / 256, 256>>>(Wq, Wk, Wv);

    cudaFuncSetAttribute(qkv_mma_kernel, cudaFuncAttributeMaxDynamicSharedMemorySize,
                         QKV_SMEM_BYTES);
    qkv_mma_kernel<<<dim3(9, M_TOTAL / 128), 256, QKV_SMEM_BYTES>>>();

    cudaFuncSetAttribute(attn_mma_kernel, cudaFuncAttributeMaxDynamicSharedMemorySize,
                         AT_SMEM_BYTES);
    attn_mma_kernel<<<dim3(SEQ / 128, BATCH), 512, AT_SMEM_BYTES>>>(out);
}

// round 16
// speedup vs baseline: 1.0897x; 1.0457x over previous
#include <cuda_runtime.h>
#include <cuda_bf16.h>
#include <cuda_fp16.h>
#include <math.h>

// Problem constants
#define BATCH 512
#define SEQ   256
#define CDIM  384
#define HDIM  384
#define M_TOTAL (BATCH * SEQ)   // 131072

// ---------------------------------------------------------------------------
// Device scratch (static: runtime allocation is forbidden)
// q/k/v single fp16 (fp16 MMA is exact given fp16 inputs; quantization 1.4e-4)
// ---------------------------------------------------------------------------
__device__ __half g_q[(size_t)M_TOTAL * HDIM];
__device__ __half g_k[(size_t)M_TOTAL * HDIM];
__device__ __half g_v[(size_t)M_TOTAL * HDIM];
__device__ __half g_x[(size_t)M_TOTAL * CDIM];          // X as fp16
__device__ __half g_w[(size_t)3 * HDIM * CDIM];         // W transposed [w][n][k], fp16

// ---------------------------------------------------------------------------
// PTX helpers (portable to plain sm_103 target — NO tcgen05)
// ---------------------------------------------------------------------------
__device__ __forceinline__ unsigned int smem_u32(const void* p) {
    unsigned int a;
    asm("{ .reg .u64 t; cvta.to.shared.u64 t, %1; cvt.u32.u64 %0, t; }" : "=r"(a) : "l"(p));
    return a;
}
__device__ __forceinline__ void cp16(unsigned int dst, const void* src) {
    asm volatile("cp.async.cg.shared.global [%0], [%1], 16;" :: "r"(dst), "l"(src));
}
__device__ __forceinline__ void cp_commit() {
    asm volatile("cp.async.commit_group;" ::: "memory");
}
__device__ __forceinline__ void cp_wait0() {
    asm volatile("cp.async.wait_group 0;" ::: "memory");
}
__device__ __forceinline__ void cp_wait1() {
    asm volatile("cp.async.wait_group 1;" ::: "memory");
}
__device__ __forceinline__ void ldsm_x4(unsigned int* r, unsigned int addr) {
    asm volatile("ldmatrix.sync.aligned.m8n8.x4.shared.b16 {%0,%1,%2,%3}, [%4];"
                 : "=r"(r[0]), "=r"(r[1]), "=r"(r[2]), "=r"(r[3]) : "r"(addr));
}
__device__ __forceinline__ void ldsm_x4_t(unsigned int* r, unsigned int addr) {
    asm volatile("ldmatrix.sync.aligned.m8n8.x4.trans.shared.b16 {%0,%1,%2,%3}, [%4];"
                 : "=r"(r[0]), "=r"(r[1]), "=r"(r[2]), "=r"(r[3]) : "r"(addr));
}
__device__ __forceinline__ void mma_fp16(float* c, const unsigned int* a,
                                         const unsigned int* b) {
    asm volatile("mma.sync.aligned.m16n8k16.row.col.f32.f16.f16.f32 "
                 "{%0,%1,%2,%3}, {%4,%5,%6,%7}, {%8,%9}, {%0,%1,%2,%3};"
                 : "+f"(c[0]), "+f"(c[1]), "+f"(c[2]), "+f"(c[3])
                 : "r"(a[0]), "r"(a[1]), "r"(a[2]), "r"(a[3]), "r"(b[0]), "r"(b[1]));
}

// ---------------------------------------------------------------------------
// Prepass 1: X fp32 -> fp16
// ---------------------------------------------------------------------------
__global__ __launch_bounds__(256) void cvt_x_kernel(const float* __restrict__ X)
{
    size_t i = (size_t)blockIdx.x * 256 + threadIdx.x;   // over M*C/4
    float4 v = ((const float4*)X)[i];
    __half2* d = (__half2*)(g_x + 4 * i);
    d[0] = __floats2half2_rn(v.x, v.y);
    d[1] = __floats2half2_rn(v.z, v.w);
}

// ---------------------------------------------------------------------------
// Prepass 2: W fp32 [k][n] -> transposed fp16 [w][n][k]
// ---------------------------------------------------------------------------
__global__ __launch_bounds__(256) void cvt_w_kernel(const float* __restrict__ Wq,
                                                    const float* __restrict__ Wk,
                                                    const float* __restrict__ Wv)
{
    int i = blockIdx.x * 256 + threadIdx.x;     // < 3*384*384
    int w = i / (CDIM * HDIM);
    int r = i - w * (CDIM * HDIM);
    int k = r / HDIM;
    int n = r - k * HDIM;
    const float* W = (w == 0) ? Wq : ((w == 1) ? Wk : Wv);
    g_w[((size_t)w * HDIM + n) * CDIM + k] = __float2half_rn(W[(size_t)k * HDIM + n]);
}

// ---------------------------------------------------------------------------
// Kernel: QKV GEMM — measured-best config (R11, ~370us):
// CTA 128x128, warp tile 32x64, K chunks of 64, 2-stage pipeline, 2 CTAs/SM.
// ---------------------------------------------------------------------------
#define ROWB   144            // padded row stride (64 fp16 = 128B data + 16 pad)
#define QTILE  (128 * ROWB)   // 18432 bytes per operand tile
#define QSTG   (2 * QTILE)    // 36864 per stage
#define QKV_SMEM_BYTES (2 * QSTG)   // 73728
#define NCHK   6

__global__ __launch_bounds__(256, 2) void qkv_mma_kernel()
{
    extern __shared__ char smem[];
    const unsigned int sb = smem_u32(smem);
    const int t    = threadIdx.x;
    const int wid  = t >> 5;
    const int lane = t & 31;

    const int nblk = blockIdx.x;           // 0..8
    const int w    = nblk / 3;             // weight select
    const int n0   = (nblk - w * 3) * 128; // col offset within weight
    const int m0   = blockIdx.y * 128;

    const __half* wsrc = g_w + (size_t)w * HDIM * CDIM;

    const int wm = (wid & 3) * 32;
    const int wn = (wid >> 2) * 64;

    const unsigned int a_lane = (unsigned)((lane & 15) * ROWB + (lane >> 4) * 16);
    const unsigned int b_lane = (unsigned)(((lane & 7) + ((lane >> 4) << 3)) * ROWB
                                           + ((lane >> 3) & 1) * 16);

    float acc[2][8][4];
    #pragma unroll
    for (int mt = 0; mt < 2; mt++)
        #pragma unroll
        for (int nt = 0; nt < 8; nt++)
            #pragma unroll
            for (int q = 0; q < 4; q++) acc[mt][nt][q] = 0.0f;

    auto load_chunk = [&](int c, int stage) {
        const unsigned int s0 = sb + (unsigned)stage * QSTG;
        #pragma unroll
        for (int it = 0; it < 4; it++) {
            int s = t + it * 256;
            int r = s >> 3, j = s & 7;
            unsigned int d = (unsigned)(r * ROWB + j * 16);
            cp16(s0 + d,         g_x + (size_t)(m0 + r) * CDIM + c * 64 + j * 8);
            cp16(s0 + QTILE + d, wsrc + (size_t)(n0 + r) * CDIM + c * 64 + j * 8);
        }
        cp_commit();
    };

    load_chunk(0, 0);
    load_chunk(1, 1);

    for (int c = 0; c < NCHK; c++) {
        if (c + 1 < NCHK) cp_wait1(); else cp_wait0();
        __syncthreads();

        const unsigned int sa = sb + (unsigned)(c & 1) * QSTG;
        const unsigned int sbb = sa + QTILE;

        #pragma unroll
        for (int kk = 0; kk < 4; kk++) {
            const unsigned int koff = kk * 32;
            unsigned int Af[2][4];
            #pragma unroll
            for (int mt = 0; mt < 2; mt++) {
                unsigned int ab = (unsigned)((wm + mt * 16) * ROWB) + koff + a_lane;
                ldsm_x4(Af[mt], sa + ab);
            }
            #pragma unroll
            for (int nt2 = 0; nt2 < 4; nt2++) {
                unsigned int bb = (unsigned)((wn + nt2 * 16) * ROWB) + koff + b_lane;
                unsigned int Bf[4];
                ldsm_x4(Bf, sbb + bb);
                #pragma unroll
                for (int mt = 0; mt < 2; mt++) {
                    mma_fp16(acc[mt][nt2 * 2 + 0], Af[mt], Bf + 0);
                    mma_fp16(acc[mt][nt2 * 2 + 1], Af[mt], Bf + 2);
                }
            }
        }
        __syncthreads();

        if (c + 2 < NCHK) load_chunk(c + 2, c & 1);
    }

    // Epilogue: fp32 acc -> fp16 q/k/v
    __half* outp = (w == 0) ? g_q : ((w == 1) ? g_k : g_v);
    #pragma unroll
    for (int mt = 0; mt < 2; mt++) {
        int r0 = m0 + wm + mt * 16 + (lane >> 2);
        #pragma unroll
        for (int nt = 0; nt < 8; nt++) {
            int cc = n0 + wn + nt * 8 + 2 * (lane & 3);
            *(__half2*)(outp + (size_t)r0 * HDIM + cc) =
                __floats2half2_rn(acc[mt][nt][0], acc[mt][nt][1]);
            *(__half2*)(outp + (size_t)(r0 + 8) * HDIM + cc) =
                __floats2half2_rn(acc[mt][nt][2], acc[mt][nt][3]);
        }
    }
}

// ---------------------------------------------------------------------------
// Kernel: causal attention — measured-best config (R14, 207.1us):
// 64 queries / 256 threads / 2 CTAs/SM, double-buffered QK and V streams,
// P->fp16 conversion fused into the softmax normalize loop.
// Smem overlay (bytes):
//   phase A stages s=0,1 at s*46080: QB +0 (9216), KB +9216 (36864) -> 92160
//   phase B: PHI fp16 64x264 at [0,33792); Ps fp32 64x260 at [40960,107520)
//   phase C: VB stages at 40960 + s*36864 -> [40960,114688)
// ---------------------------------------------------------------------------
#define AT_STGS  46080u
#define AT_QB    0u
#define AT_KB    9216u
#define AT_PHI   0u
#define AT_PS    40960u
#define AT_VB0   40960u
#define AT_VBS   36864u
#define AT_SMEM_BYTES 114688

__global__ __launch_bounds__(256, 2) void attn_mma_kernel(float* __restrict__ Out)
{
    extern __shared__ char smem[];
    const unsigned int sb = smem_u32(smem);
    const int t    = threadIdx.x;
    const int wid  = t >> 5;
    const int lane = t & 31;
    const int bq   = blockIdx.x;          // 0..3
    const int b    = blockIdx.y;          // 0..511
    const int q0   = bq * 64;
    const int Kv   = (bq + 1) * 64;       // valid keys
    const float scl = rsqrtf((float)HDIM);

    const int wm = (wid & 1) * 32;        // warp m offset (2 m-warps)
    const int wn = (wid >> 1) * 64;       // warp n offset, phase A (4 n-warps)

    const unsigned int a_lane = (unsigned)((lane & 15) * ROWB + (lane >> 4) * 16);
    const unsigned int b_lane = (unsigned)(((lane & 7) + ((lane >> 4) << 3)) * ROWB
                                           + ((lane >> 3) & 1) * 16);
    const unsigned int p_lane = (unsigned)((lane & 15) * 528 + (lane >> 4) * 16);
    const unsigned int v_lane = (unsigned)((lane & 15) * ROWB + (lane >> 4) * 16);

    // ---------------- Phase A: S = Q K^T (fp16, double-buffered) -----------
    float sacc[2][8][4];
    #pragma unroll
    for (int mt = 0; mt < 2; mt++)
        #pragma unroll
        for (int nt = 0; nt < 8; nt++)
            #pragma unroll
            for (int q = 0; q < 4; q++) sacc[mt][nt][q] = 0.0f;

    const bool sact = (wn < Kv);

    auto load_qk = [&](int hc, int stg) {
        const unsigned int s0 = sb + (unsigned)stg * AT_STGS;
        #pragma unroll
        for (int it = 0; it < 2; it++) {
            int s = t + it * 256;
            int r = s >> 3, j = s & 7;
            unsigned int d = (unsigned)(r * ROWB + j * 16);
            cp16(s0 + AT_QB + d, g_q + (size_t)(b * SEQ + q0 + r) * HDIM + hc * 64 + j * 8);
        }
        #pragma unroll
        for (int it = 0; it < 8; it++) {
            int s = t + it * 256;
            int r = s >> 3, j = s & 7;
            if (r < Kv) {
                unsigned int d = (unsigned)(r * ROWB + j * 16);
                cp16(s0 + AT_KB + d, g_k + (size_t)(b * SEQ + r) * HDIM + hc * 64 + j * 8);
            }
        }
        cp_commit();
    };

    load_qk(0, 0);

    for (int hc = 0; hc < 6; hc++) {
        const int stg = hc & 1;
        if (hc + 1 < 6) load_qk(hc + 1, stg ^ 1);
        if (hc + 1 < 6) cp_wait1(); else cp_wait0();
        __syncthreads();

        if (sact) {
            const unsigned int sq = sb + (unsigned)stg * AT_STGS + AT_QB;
            const unsigned int sk = sb + (unsigned)stg * AT_STGS + AT_KB;
            #pragma unroll
            for (int kk = 0; kk < 4; kk++) {
                const unsigned int koff = kk * 32;
                unsigned int Af[2][4];
                #pragma unroll
                for (int mt = 0; mt < 2; mt++) {
                    unsigned int ab = (unsigned)((wm + mt * 16) * ROWB) + koff + a_lane;
                    ldsm_x4(Af[mt], sq + ab);
                }
                #pragma unroll
                for (int nt2 = 0; nt2 < 4; nt2++) {
                    unsigned int bb = (unsigned)((wn + nt2 * 16) * ROWB) + koff + b_lane;
                    unsigned int Bf[4];
                    ldsm_x4(Bf, sk + bb);
                    #pragma unroll
                    for (int mt = 0; mt < 2; mt++) {
                        mma_fp16(sacc[mt][nt2 * 2 + 0], Af[mt], Bf + 0);
                        mma_fp16(sacc[mt][nt2 * 2 + 1], Af[mt], Bf + 2);
                    }
                }
            }
        }
        __syncthreads();
    }

    // ---------------- Phase B: scatter S, softmax (+fused fp16 convert) ----
    float* Ps = (float*)(smem + AT_PS);
    #pragma unroll
    for (int mt = 0; mt < 2; mt++) {
        int r = wm + mt * 16 + (lane >> 2);
        #pragma unroll
        for (int nt = 0; nt < 8; nt++) {
            int cc = wn + nt * 8 + 2 * (lane & 3);
            *(float2*)&Ps[r * 260 + cc] =
                make_float2(sacc[mt][nt][0] * scl, sacc[mt][nt][1] * scl);
            *(float2*)&Ps[(r + 8) * 260 + cc] =
                make_float2(sacc[mt][nt][2] * scl, sacc[mt][nt][3] * scl);
        }
    }
    __syncthreads();

    {
        __half* Ph = (__half*)(smem + AT_PHI);
        const int wq = wid;                 // warp handles rows wq*8 .. wq*8+7
        for (int rr = 0; rr < 8; rr++) {
            int r  = wq * 8 + rr;
            int qg = q0 + r;                // valid keys: 0..qg
            float* row = Ps + (size_t)r * 260;
            float m = -1e30f;
            for (int j = lane; j <= qg; j += 32) m = fmaxf(m, row[j]);
            #pragma unroll
            for (int off = 16; off > 0; off >>= 1)
                m = fmaxf(m, __shfl_xor_sync(0xffffffffu, m, off));
            float s = 0.0f;
            for (int j = lane; j <= qg; j += 32) {
                float e = __expf(row[j] - m);
                row[j] = e;
                s += e;
            }
            #pragma unroll
            for (int off = 16; off > 0; off >>= 1)
                s += __shfl_xor_sync(0xffffffffu, s, off);
            float inv = 1.0f / s;
            // normalize + convert to fp16 in one pass (PHI overlays dead QB/KB)
            __half* prow = Ph + (size_t)r * 264;
            for (int j = lane; j < Kv; j += 32)
                prow[j] = (j <= qg) ? __float2half_rn(row[j] * inv) : __half(0);
        }
    }
    __syncthreads();

    // ---------------- Phase C: O = P V (fp16, double-buffered V) -----------
    const int wnc = (wid >> 1) * 16;        // warp n offset within 64-col chunk
    const int nks = Kv >> 4;                // k16 steps over keys

    auto load_v = [&](int hc, int stg) {
        const unsigned int v0 = sb + AT_VB0 + (unsigned)stg * AT_VBS;
        #pragma unroll
        for (int it = 0; it < 8; it++) {
            int s = t + it * 256;
            int r = s >> 3, j = s & 7;
            if (r < Kv) {
                unsigned int d = (unsigned)(r * ROWB + j * 16);
                cp16(v0 + d, g_v + (size_t)(b * SEQ + r) * HDIM + hc * 64 + j * 8);
            }
        }
        cp_commit();
    };

    load_v(0, 0);

    for (int hc = 0; hc < 6; hc++) {
        const int stg = hc & 1;
        if (hc + 1 < 6) load_v(hc + 1, stg ^ 1);
        if (hc + 1 < 6) cp_wait1(); else cp_wait0();
        __syncthreads();

        const unsigned int sv = sb + AT_VB0 + (unsigned)stg * AT_VBS;

        float oacc[2][2][4];
        #pragma unroll
        for (int mt = 0; mt < 2; mt++)
            #pragma unroll
            for (int nt = 0; nt < 2; nt++)
                #pragma unroll
                for (int q = 0; q < 4; q++) oacc[mt][nt][q] = 0.0f;

        for (int ks = 0; ks < nks; ks++) {
            unsigned int Phf[2][4];
            #pragma unroll
            for (int mt = 0; mt < 2; mt++) {
                unsigned int pa = (unsigned)((wm + mt * 16) * 528) + ks * 32 + p_lane;
                ldsm_x4(Phf[mt], sb + AT_PHI + pa);
            }
            unsigned int Vh[4];
            unsigned int va = (unsigned)(ks * 16 * ROWB) + (unsigned)(wnc * 2) + v_lane;
            ldsm_x4_t(Vh, sv + va);
            #pragma unroll
            for (int mt = 0; mt < 2; mt++) {
                #pragma unroll
                for (int nt = 0; nt < 2; nt++) {
                    mma_fp16(oacc[mt][nt], Phf[mt], Vh + nt * 2);
                }
            }
        }

        // write O chunk
        #pragma unroll
        for (int mt = 0; mt < 2; mt++) {
            int gr = b * SEQ + q0 + wm + mt * 16 + (lane >> 2);
            #pragma unroll
            for (int nt = 0; nt < 2; nt++) {
                int gc = hc * 64 + wnc + nt * 8 + 2 * (lane & 3);
                *(float2*)(Out + (size_t)gr * HDIM + gc) =
                    make_float2(oacc[mt][nt][0], oacc[mt][nt][1]);
                *(float2*)(Out + (size_t)(gr + 8) * HDIM + gc) =
                    make_float2(oacc[mt][nt][2], oacc[mt][nt][3]);
            }
        }
        __syncthreads();
    }
}

// ---------------------------------------------------------------------------
// Launch
// ---------------------------------------------------------------------------
extern "C" void kernel_launch(void* const* d_in, const int* in_sizes, int n_in,
                              void* d_out, int out_size)
{
    const float* x  = (const float*)d_in[0];
    const float* Wq = (const float*)d_in[1];
    const float* Wk = (const float*)d_in[2];
    const float* Wv = (const float*)d_in[3];
    float* out = (float*)d_out;

    cvt_x_kernel<<<(M_TOTAL * CDIM) / 1024, 256>>>(x);
    cvt_w_kernel<<<(3 * CDIM * HDIM) / 256, 256>>>(Wq, Wk, Wv);

    cudaFuncSetAttribute(qkv_mma_kernel, cudaFuncAttributeMaxDynamicSharedMemorySize,
                         QKV_SMEM_BYTES);
    qkv_mma_kernel<<<dim3(9, M_TOTAL / 128), 256, QKV_SMEM_BYTES>>>();

    cudaFuncSetAttribute(attn_mma_kernel, cudaFuncAttributeMaxDynamicSharedMemorySize,
                         AT_SMEM_BYTES);
    attn_mma_kernel<<<dim3(SEQ / 64, BATCH), 256, AT_SMEM_BYTES>>>(out);
}